// round 16
// baseline (speedup 1.0000x reference)
#include <cuda_runtime.h>
#include <cuda_bf16.h>
#include <cstdint>
#include <math.h>

#define NN 10000
#define EE 160000
#define ET (EE + NN)
#define HH 8
#define DD 128
#define HD 1024   // H*D
#define SETUP_BLKS 40     // (NN+255)/256
#define PREPB_BLKS 144

// ---------------- scratch (static device allocations; no cudaMalloc) --------
__device__ int   d_is64;
__device__ int   d_done;
__device__ int   d_deg[NN];
__device__ int   d_cursor[NN];
__device__ int   d_rowptr[NN + 1];
__device__ int   d_colsrc[ET];
__device__ __align__(16) float d_as[NN * HH];
__device__ __align__(16) float d_ad[NN * HH];
__device__ __align__(16) float d_dinv[NN];
__device__ __align__(16) float d_snode[NN * 32];   // [N][H][4]
__device__ __align__(16) float d_t1[NN * DD];
__device__ __align__(16) float d_t2[NN * DD];
__device__ __align__(16) __nv_bfloat16 d_h1hi[NN * DD];
__device__ __align__(16) __nv_bfloat16 d_h1lo[NN * DD];
__device__ __align__(16) __nv_bfloat16 d_b1hi[DD * HD];  // w1^T split [128][1024]
__device__ __align__(16) __nv_bfloat16 d_b1lo[DD * HD];
__device__ __align__(16) __nv_bfloat16 d_b2hi[DD * DD];  // w2^T split [128][128]
__device__ __align__(16) __nv_bfloat16 d_b2lo[DD * DD];
__device__ __align__(16) float d_csrc[32];         // [H][4]
__device__ __align__(16) float d_cdst[32];

// ---------------- helpers ---------------------------------------------------
__device__ __forceinline__ float gelu_exact(float v) {
    return 0.5f * v * (1.0f + erff(v * 0.70710678118654752440f));
}

__device__ __forceinline__ void ldsm4(uint32_t* r, uint32_t addr) {
    asm volatile("ldmatrix.sync.aligned.m8n8.x4.shared.b16 {%0,%1,%2,%3}, [%4];"
                 : "=r"(r[0]), "=r"(r[1]), "=r"(r[2]), "=r"(r[3]) : "r"(addr));
}
__device__ __forceinline__ void ldsm2(uint32_t* r, uint32_t addr) {
    asm volatile("ldmatrix.sync.aligned.m8n8.x2.shared.b16 {%0,%1}, [%2];"
                 : "=r"(r[0]), "=r"(r[1]) : "r"(addr));
}
__device__ __forceinline__ void mma_bf16(float* c, const uint32_t* a, const uint32_t* b) {
    asm volatile("mma.sync.aligned.m16n8k16.row.col.f32.bf16.bf16.f32 "
                 "{%0,%1,%2,%3}, {%4,%5,%6,%7}, {%8,%9}, {%0,%1,%2,%3};"
                 : "+f"(c[0]), "+f"(c[1]), "+f"(c[2]), "+f"(c[3])
                 : "r"(a[0]), "r"(a[1]), "r"(a[2]), "r"(a[3]), "r"(b[0]), "r"(b[1]));
}
__device__ __forceinline__ void cp16(void* dst, const void* src) {
    uint32_t d = (uint32_t)__cvta_generic_to_shared(dst);
    asm volatile("cp.async.ca.shared.global [%0], [%1], 16;" :: "r"(d), "l"(src) : "memory");
}

// ---------------- setup + prepB (merged) -------------------------------------
// Blocks [0, SETUP_BLKS): deg/cursor init; block 0 also: dtype detect, prep_c,
// ticket reset. Blocks [SETUP_BLKS, SETUP_BLKS+PREPB_BLKS): coalesced
// transpose + bf16 split of w1/w2.
__global__ void k_setup(const int* __restrict__ w,
                        const float* __restrict__ gw,
                        const float* __restrict__ asrc,
                        const float* __restrict__ adst,
                        const float* __restrict__ w1,
                        const float* __restrict__ w2) {
    __shared__ float sm[32][33];
    __shared__ int nz;
    int bid = blockIdx.x;
    int t = threadIdx.x;
    if (bid < SETUP_BLKS) {
        int i = bid * 256 + t;
        if (i < NN) { d_deg[i] = 1; d_cursor[i] = 0; }
        if (bid == 0) {
            if (t == 0) { nz = 0; d_done = 0; }
            __syncthreads();
            if (t < 128 && w[2 * t + 1] != 0) atomicOr(&nz, 1);
            __syncthreads();
            if (t == 0) d_is64 = nz ? 0 : 1;
            if (t < 64) {
                int which = t >> 5;
                int idx = t & 31;
                int h = idx >> 2, f = idx & 3;
                const float* att = which ? adst : asrc;
                float s = 0.0f;
                for (int d = 0; d < DD; d++)
                    s += gw[f * HD + h * DD + d] * att[h * DD + d];
                if (which) d_cdst[idx] = s; else d_csrc[idx] = s;
            }
        }
        return;
    }
    // prepB part
    int pb = bid - SETUP_BLKS;
    const float* src;
    __nv_bfloat16 *bhi, *blo;
    int K, kt, nt;
    if (pb < 128) {
        src = w1; bhi = d_b1hi; blo = d_b1lo; K = HD;
        kt = pb & 31; nt = pb >> 5;
    } else {
        src = w2; bhi = d_b2hi; blo = d_b2lo; K = DD;
        int r = pb - 128;
        kt = r & 3; nt = r >> 2;
    }
    int tx = t & 31, ty = t >> 5;
#pragma unroll
    for (int r = 0; r < 4; r++) {
        int k = kt * 32 + ty + r * 8;
        int n = nt * 32 + tx;
        sm[ty + r * 8][tx] = src[k * 128 + n];
    }
    __syncthreads();
#pragma unroll
    for (int r = 0; r < 4; r++) {
        int n = nt * 32 + ty + r * 8;
        int k = kt * 32 + tx;
        float v = sm[tx][ty + r * 8];
        __nv_bfloat16 h = __float2bfloat16(v);
        bhi[(size_t)n * K + k] = h;
        blo[(size_t)n * K + k] = __float2bfloat16(v - __bfloat162float(h));
    }
}

// ---------------- count + fused last-block scan ------------------------------
#define COUNT_BLKS ((EE + 1023) / 1024)   // 4 edges/thread, 256 threads

__global__ void k_count(const int* __restrict__ w) {
    int e0 = (blockIdx.x * 256 + threadIdx.x) * 4;
    int is64 = d_is64;
    if (e0 < EE) {
#pragma unroll
        for (int j = 0; j < 4; j++) {
            int e = e0 + j;
            if (e < EE) {
                int dd = is64 ? w[2 * (EE + e)] : w[EE + e];
                if ((unsigned)dd < NN) atomicAdd(&d_deg[dd], 1);
            }
        }
    }
    __threadfence();
    __shared__ int lastblk;
    if (threadIdx.x == 0) {
        int ticket = atomicAdd(&d_done, 1);
        lastblk = (ticket == COUNT_BLKS - 1);
    }
    __syncthreads();
    if (!lastblk) return;

    // scan 10000 degs with 256 threads, C=40
    __shared__ int wsum[8];
    int t = threadIdx.x;
    const int C = 40;
    int base = t * C;
    int v[C];
    int sum = 0;
#pragma unroll
    for (int i = 0; i < C; i++) {
        int idx = base + i;
        v[i] = (idx < NN) ? d_deg[idx] : 0;
        sum += v[i];
    }
    int lane = t & 31, wp = t >> 5;
    int s = sum;
#pragma unroll
    for (int off = 1; off < 32; off <<= 1) {
        int o = __shfl_up_sync(0xFFFFFFFFu, s, off);
        if (lane >= off) s += o;
    }
    if (lane == 31) wsum[wp] = s;
    __syncthreads();
    if (wp == 0) {
        int ws = (lane < 8) ? wsum[lane] : 0;
#pragma unroll
        for (int off = 1; off < 8; off <<= 1) {
            int o = __shfl_up_sync(0xFFFFFFFFu, ws, off);
            if (lane >= off) ws += o;
        }
        if (lane < 8) wsum[lane] = ws;
    }
    __syncthreads();
    int run = s - sum + (wp > 0 ? wsum[wp - 1] : 0);   // exclusive prefix
#pragma unroll
    for (int i = 0; i < C; i++) {
        int idx = base + i;
        if (idx < NN) { d_rowptr[idx] = run; run += v[i]; }
    }
    if (t == 255) d_rowptr[NN] = wsum[7];
}

// ---------------- fill CSR + per-node scores/dinv (merged) ------------------
__global__ void k_fillnode(const int* __restrict__ w, const float* __restrict__ x) {
    int t = blockIdx.x * blockDim.x + threadIdx.x;
    if (t < NN) {
        float4 xv = ((const float4*)x)[t];
#pragma unroll
        for (int h = 0; h < HH; h++) {
            d_as[t * 8 + h] = xv.x * d_csrc[h * 4 + 0] + xv.y * d_csrc[h * 4 + 1]
                            + xv.z * d_csrc[h * 4 + 2] + xv.w * d_csrc[h * 4 + 3];
            d_ad[t * 8 + h] = xv.x * d_cdst[h * 4 + 0] + xv.y * d_cdst[h * 4 + 1]
                            + xv.z * d_cdst[h * 4 + 2] + xv.w * d_cdst[h * 4 + 3];
        }
        d_dinv[t] = rsqrtf((float)d_deg[t]);
    }
    if (t >= ET) return;
    int is64 = d_is64;
    int s, dd;
    if (t < EE) {
        s  = is64 ? w[2 * t]        : w[t];
        dd = is64 ? w[2 * (EE + t)] : w[EE + t];
    } else {
        s = t - EE; dd = s;           // self loop
    }
    if ((unsigned)dd >= NN || (unsigned)s >= NN) return;
    int pos = atomicAdd(&d_cursor[dd], 1);
    d_colsrc[d_rowptr[dd] + pos] = s;
}

// ---------------- GAT softmax (no max-shift; |e| << 1) + rank-4 agg ---------
__global__ void k_gat(const float* __restrict__ x) {
    int node = blockIdx.x * 32 + (threadIdx.x >> 3);
    int h = threadIdx.x & 7;
    if (node >= NN) return;
    int r0 = d_rowptr[node], r1 = d_rowptr[node + 1];
    float ad = d_ad[node * 8 + h];
    float den = 0.0f;
    float t0 = 0.0f, t1 = 0.0f, t2 = 0.0f, t3 = 0.0f;
    int i = r0;
    for (; i + 2 <= r1; i += 2) {
        int s0 = d_colsrc[i], s1 = d_colsrc[i + 1];
        float e0 = d_as[s0 * 8 + h] + ad;
        float e1 = d_as[s1 * 8 + h] + ad;
        float4 xv0 = ((const float4*)x)[s0];
        float4 xv1 = ((const float4*)x)[s1];
        e0 = e0 > 0.0f ? e0 : 0.2f * e0;
        e1 = e1 > 0.0f ? e1 : 0.2f * e1;
        float ex0 = __expf(e0), ex1 = __expf(e1);
        den += ex0 + ex1;
        t0 += ex0 * xv0.x + ex1 * xv1.x;
        t1 += ex0 * xv0.y + ex1 * xv1.y;
        t2 += ex0 * xv0.z + ex1 * xv1.z;
        t3 += ex0 * xv0.w + ex1 * xv1.w;
    }
    if (i < r1) {
        int s0 = d_colsrc[i];
        float e0 = d_as[s0 * 8 + h] + ad;
        e0 = e0 > 0.0f ? e0 : 0.2f * e0;
        float ex0 = __expf(e0);
        float4 xv0 = ((const float4*)x)[s0];
        den += ex0;
        t0 += ex0 * xv0.x; t1 += ex0 * xv0.y;
        t2 += ex0 * xv0.z; t3 += ex0 * xv0.w;
    }
    float inv = 1.0f / den;
    float* sp = &d_snode[node * 32 + h * 4];
    sp[0] = t0 * inv; sp[1] = t1 * inv; sp[2] = t2 * inv; sp[3] = t3 * inv;
}

// ---------------- split-bf16 mma.sync GEMM (round-12 winner config) ---------
#define OFF_AH 0
#define OFF_AL 2048
#define OFF_BH 4096
#define OFF_BL 10240
#define STAGE_BYTES 16384

__device__ __forceinline__ void gen_a(char* stg, const float* Ssh,
                                      const float* __restrict__ gw,
                                      const float* __restrict__ gb,
                                      int k0, int t) {
    int m = t >> 1, half = t & 1;
    const float* sp = Ssh + m * 36 + ((k0 >> 7) << 2);
    float s0 = sp[0], s1 = sp[1], s2 = sp[2], s3 = sp[3];
    int jb = k0 + half * 8;
    uint32_t hi4[4], lo4[4];
#pragma unroll
    for (int q = 0; q < 4; q++) {
        uint32_t hh = 0, ll = 0;
#pragma unroll
        for (int u = 0; u < 2; u++) {
            int j = jb + q * 2 + u;
            float a = __ldg(gb + j) + s0 * __ldg(gw + j) + s1 * __ldg(gw + HD + j)
                    + s2 * __ldg(gw + 2 * HD + j) + s3 * __ldg(gw + 3 * HD + j);
            float v = gelu_exact(a);
            __nv_bfloat16 h = __float2bfloat16(v);
            __nv_bfloat16 l = __float2bfloat16(v - __bfloat162float(h));
            hh |= (uint32_t)__bfloat16_as_ushort(h) << (u * 16);
            ll |= (uint32_t)__bfloat16_as_ushort(l) << (u * 16);
        }
        hi4[q] = hh; lo4[q] = ll;
    }
    *(uint4*)(stg + OFF_AH + half * 1024 + m * 16) = make_uint4(hi4[0], hi4[1], hi4[2], hi4[3]);
    *(uint4*)(stg + OFF_AL + half * 1024 + m * 16) = make_uint4(lo4[0], lo4[1], lo4[2], lo4[3]);
}

__device__ __forceinline__ void load_b(char* stg, const __nv_bfloat16* gBhi,
                                       const __nv_bfloat16* gBlo, int K, int k0, int t) {
#pragma unroll
    for (int i = 0; i < 4; i++) {
        int idx = t + i * 128;          // 0..511
        int hilo = idx >> 8;
        int r = idx & 255;
        int n = r >> 1, half = r & 1;
        char* dst = stg + (hilo ? OFF_BL : OFF_BH) + n * 48 + half * 16;
        const __nv_bfloat16* src = (hilo ? gBlo : gBhi) + (size_t)n * K + k0 + half * 8;
        cp16(dst, src);
    }
}

__device__ __forceinline__ void load_a(char* stg, int K, int k0, int t, int bm, int M) {
#pragma unroll
    for (int i = 0; i < 2; i++) {
        int idx = t + i * 128;          // 0..255
        int hilo = idx >> 7;
        int r = idx & 127;
        int m = r >> 1, half = r & 1;
        int mg = bm + m; if (mg >= M) mg = M - 1;
        char* dst = stg + (hilo ? OFF_AL : OFF_AH) + half * 1024 + m * 16;
        const __nv_bfloat16* src = (hilo ? d_h1lo : d_h1hi) + (size_t)mg * K + k0 + half * 8;
        cp16(dst, src);
    }
}

__global__ void __launch_bounds__(128) k_mma(int K, int which, int M,
                                             const float* __restrict__ gw,
                                             const float* __restrict__ gb) {
    __shared__ __align__(16) char stage[2 * STAGE_BYTES];
    __shared__ __align__(16) float Ssh[64 * 36];
    int t = threadIdx.x;
    int lane = t & 31, wrp = t >> 5;
    int bm = blockIdx.x * 64;
    const __nv_bfloat16* gBhi = which ? d_b2hi : d_b1hi;
    const __nv_bfloat16* gBlo = which ? d_b2lo : d_b1lo;
    float* C = which ? d_t2 : d_t1;

    if (which == 0) {
        for (int i = t; i < 512; i += 128) {
            int row = i >> 3, q = i & 7;
            int g = bm + row;
            float4 v = (g < M) ? ((const float4*)d_snode)[g * 8 + q]
                               : make_float4(0.f, 0.f, 0.f, 0.f);
            *(float4*)&Ssh[row * 36 + q * 4] = v;
        }
    }
    __syncthreads();

    const int NC = K >> 4;

    // prologue: fill stage 0 (chunk 0)
    load_b(stage, gBhi, gBlo, K, 0, t);
    if (which) load_a(stage, K, 0, t, bm, M);
    asm volatile("cp.async.commit_group;" ::: "memory");
    if (!which) gen_a(stage, Ssh, gw, gb, 0, t);
    asm volatile("cp.async.wait_group 0;" ::: "memory");
    __syncthreads();

    float acc[16][4];
#pragma unroll
    for (int nt = 0; nt < 16; nt++) {
        acc[nt][0] = 0.f; acc[nt][1] = 0.f; acc[nt][2] = 0.f; acc[nt][3] = 0.f;
    }

    uint32_t l15 = lane & 15;
    uint32_t aoff = (wrp * 16 + l15) * 16 + ((uint32_t)(lane >> 4) << 10);
    uint32_t boff = (l15 < 8) ? l15 * 48 : (l15 - 8) * 48 + 16;

    for (int c = 0; c < NC; c++) {
        int cur = c & 1;
        char* stg = stage + cur * STAGE_BYTES;
        if (c + 1 < NC) {
            char* nstg = stage + (cur ^ 1) * STAGE_BYTES;
            int nk0 = (c + 1) << 4;
            load_b(nstg, gBhi, gBlo, K, nk0, t);
            if (which) load_a(nstg, K, nk0, t, bm, M);
            asm volatile("cp.async.commit_group;" ::: "memory");
            if (!which) gen_a(nstg, Ssh, gw, gb, nk0, t);
        }
        uint32_t sb = (uint32_t)__cvta_generic_to_shared(stg);
        uint32_t ah[4], al[4];
        ldsm4(ah, sb + OFF_AH + aoff);
        ldsm4(al, sb + OFF_AL + aoff);
#pragma unroll
        for (int nt = 0; nt < 16; nt++) {
            uint32_t bh[2], bl[2];
            ldsm2(bh, sb + OFF_BH + nt * 384 + boff);
            ldsm2(bl, sb + OFF_BL + nt * 384 + boff);
            mma_bf16(acc[nt], ah, bh);
            mma_bf16(acc[nt], ah, bl);
            mma_bf16(acc[nt], al, bh);
        }
        if (c + 1 < NC)
            asm volatile("cp.async.wait_group 0;" ::: "memory");
        __syncthreads();
    }

    // epilogue: acc -> C (fp32)
    int mrow = bm + wrp * 16 + lane / 4;
    int nbase = (lane % 4) * 2;
#pragma unroll
    for (int nt = 0; nt < 16; nt++) {
        int n0 = nt * 8 + nbase;
        if (mrow < M)
            *(float2*)&C[(size_t)mrow * 128 + n0] = make_float2(acc[nt][0], acc[nt][1]);
        if (mrow + 8 < M)
            *(float2*)&C[(size_t)(mrow + 8) * 128 + n0] = make_float2(acc[nt][2], acc[nt][3]);
    }
}

// ---------------- GCN aggregation (unroll 2 for MLP) -------------------------
template <bool FIRST>
__global__ void k_agg(const float* __restrict__ bias, float* __restrict__ ext_out) {
    const float* tin = FIRST ? d_t1 : d_t2;
    int node = blockIdx.x * 8 + (threadIdx.x >> 5);
    int lane = threadIdx.x & 31;
    if (node >= NN) return;
    int r0 = d_rowptr[node], r1 = d_rowptr[node + 1];
    float4 acc = make_float4(0.f, 0.f, 0.f, 0.f);
    const float4* t4 = (const float4*)tin;
    int i = r0;
    for (; i + 2 <= r1; i += 2) {
        int s0 = d_colsrc[i], s1 = d_colsrc[i + 1];
        float w0 = d_dinv[s0], w1 = d_dinv[s1];
        float4 v0 = t4[s0 * 32 + lane];
        float4 v1 = t4[s1 * 32 + lane];
        acc.x += w0 * v0.x + w1 * v1.x;
        acc.y += w0 * v0.y + w1 * v1.y;
        acc.z += w0 * v0.z + w1 * v1.z;
        acc.w += w0 * v0.w + w1 * v1.w;
    }
    if (i < r1) {
        int s0 = d_colsrc[i];
        float w0 = d_dinv[s0];
        float4 v0 = t4[s0 * 32 + lane];
        acc.x += w0 * v0.x; acc.y += w0 * v0.y;
        acc.z += w0 * v0.z; acc.w += w0 * v0.w;
    }
    float dn = d_dinv[node];
    float4 b = ((const float4*)bias)[lane];
    float4 r;
    r.x = acc.x * dn + b.x;
    r.y = acc.y * dn + b.y;
    r.z = acc.z * dn + b.z;
    r.w = acc.w * dn + b.w;
    if (FIRST) {
        float vv[4];
        vv[0] = gelu_exact(r.x); vv[1] = gelu_exact(r.y);
        vv[2] = gelu_exact(r.z); vv[3] = gelu_exact(r.w);
        int base = node * DD + lane * 4;
#pragma unroll
        for (int c = 0; c < 4; c++) {
            __nv_bfloat16 h = __float2bfloat16(vv[c]);
            d_h1hi[base + c] = h;
            d_h1lo[base + c] = __float2bfloat16(vv[c] - __bfloat162float(h));
        }
    } else {
        ((float4*)ext_out)[node * 32 + lane] = r;
    }
}

// ---------------- launch -----------------------------------------------------
extern "C" void kernel_launch(void* const* d_in, const int* in_sizes, int n_in,
                              void* d_out, int out_size) {
    const float* x       = (const float*)d_in[0];
    const int*   eiw     = (const int*)d_in[1];      // words; dtype detected on device
    const float* gat_w   = (const float*)d_in[2];
    const float* att_src = (const float*)d_in[3];
    const float* att_dst = (const float*)d_in[4];
    const float* gat_b   = (const float*)d_in[5];
    const float* w1      = (const float*)d_in[6];
    const float* b1      = (const float*)d_in[7];
    const float* w2      = (const float*)d_in[8];
    const float* b2      = (const float*)d_in[9];
    float* out = (float*)d_out;

    k_setup<<<SETUP_BLKS + PREPB_BLKS, 256>>>(eiw, gat_w, att_src, att_dst, w1, w2);
    k_count<<<COUNT_BLKS, 256>>>(eiw);
    k_fillnode<<<(ET + 255) / 256, 256>>>(eiw, x);
    k_gat<<<(NN + 31) / 32, 256>>>(x);
    k_mma<<<(NN + 63) / 64, 128>>>(HD, 0, NN, gat_w, gat_b);
    k_agg<true><<<(NN + 7) / 8, 256>>>(b1, nullptr);
    k_mma<<<(NN + 63) / 64, 128>>>(DD, 1, NN, nullptr, nullptr);
    k_agg<false><<<(NN + 7) / 8, 256>>>(b2, out);
}

// round 17
// speedup vs baseline: 1.5213x; 1.5213x over previous
#include <cuda_runtime.h>
#include <cuda_bf16.h>
#include <cstdint>
#include <math.h>

#define NN 10000
#define EE 160000
#define ET (EE + NN)
#define HH 8
#define DD 128
#define HD 1024   // H*D

// ---------------- scratch (static device allocations; no cudaMalloc) --------
__device__ int   d_is64;
__device__ int   d_deg[NN];
__device__ int   d_cursor[NN];
__device__ int   d_rowptr[NN + 1];
__device__ int   d_colsrc[ET];
__device__ __align__(16) float d_as[NN * HH];
__device__ __align__(16) float d_ad[NN * HH];
__device__ __align__(16) float d_dinv[NN];
__device__ __align__(16) float d_snode[NN * 32];   // [N][H][4]
__device__ __align__(16) float d_t1[NN * DD];
__device__ __align__(16) float d_t2[NN * DD];
__device__ __align__(16) __nv_bfloat16 d_h1hi[NN * DD];
__device__ __align__(16) __nv_bfloat16 d_h1lo[NN * DD];
__device__ __align__(16) __nv_bfloat16 d_b1hi[DD * HD];  // w1^T split [128][1024]
__device__ __align__(16) __nv_bfloat16 d_b1lo[DD * HD];
__device__ __align__(16) __nv_bfloat16 d_b2hi[DD * DD];  // w2^T split [128][128]
__device__ __align__(16) __nv_bfloat16 d_b2lo[DD * DD];
__device__ __align__(16) float d_csrc[32];         // [H][4]
__device__ __align__(16) float d_cdst[32];

// ---------------- helpers ---------------------------------------------------
__device__ __forceinline__ float gelu_exact(float v) {
    return 0.5f * v * (1.0f + erff(v * 0.70710678118654752440f));
}

__device__ __forceinline__ void ldsm4(uint32_t* r, uint32_t addr) {
    asm volatile("ldmatrix.sync.aligned.m8n8.x4.shared.b16 {%0,%1,%2,%3}, [%4];"
                 : "=r"(r[0]), "=r"(r[1]), "=r"(r[2]), "=r"(r[3]) : "r"(addr));
}
__device__ __forceinline__ void ldsm2(uint32_t* r, uint32_t addr) {
    asm volatile("ldmatrix.sync.aligned.m8n8.x2.shared.b16 {%0,%1}, [%2];"
                 : "=r"(r[0]), "=r"(r[1]) : "r"(addr));
}
__device__ __forceinline__ void mma_bf16(float* c, const uint32_t* a, const uint32_t* b) {
    asm volatile("mma.sync.aligned.m16n8k16.row.col.f32.bf16.bf16.f32 "
                 "{%0,%1,%2,%3}, {%4,%5,%6,%7}, {%8,%9}, {%0,%1,%2,%3};"
                 : "+f"(c[0]), "+f"(c[1]), "+f"(c[2]), "+f"(c[3])
                 : "r"(a[0]), "r"(a[1]), "r"(a[2]), "r"(a[3]), "r"(b[0]), "r"(b[1]));
}
__device__ __forceinline__ void cp16(void* dst, const void* src) {
    uint32_t d = (uint32_t)__cvta_generic_to_shared(dst);
    asm volatile("cp.async.ca.shared.global [%0], [%1], 16;" :: "r"(d), "l"(src) : "memory");
}

// ---------------- setup: dtype detect + prep_c + deg init -------------------
__global__ void k_setup(const int* __restrict__ w,
                        const float* __restrict__ gw,
                        const float* __restrict__ asrc,
                        const float* __restrict__ adst) {
    int i = blockIdx.x * blockDim.x + threadIdx.x;
    if (i < NN) { d_deg[i] = 1; d_cursor[i] = 0; }
    if (blockIdx.x == 0) {
        __shared__ int nz;
        if (threadIdx.x == 0) nz = 0;
        __syncthreads();
        if (threadIdx.x < 128 && w[2 * threadIdx.x + 1] != 0) atomicOr(&nz, 1);
        __syncthreads();
        if (threadIdx.x == 0) d_is64 = nz ? 0 : 1;
        int t = threadIdx.x;
        if (t < 64) {
            int which = t >> 5;
            int idx = t & 31;
            int h = idx >> 2, f = idx & 3;
            const float* att = which ? adst : asrc;
            float s = 0.0f;
            for (int d = 0; d < DD; d++)
                s += gw[f * HD + h * DD + d] * att[h * DD + d];
            if (which) d_cdst[idx] = s; else d_csrc[idx] = s;
        }
    }
}

// ---------------- B prep: COALESCED smem tile transpose + bf16 split --------
__global__ void k_prepB(const float* __restrict__ w1, const float* __restrict__ w2) {
    __shared__ float sm[32][33];
    int bid = blockIdx.x;
    const float* src;
    __nv_bfloat16 *bhi, *blo;
    int K, kt, nt;
    if (bid < 128) {
        src = w1; bhi = d_b1hi; blo = d_b1lo; K = HD;
        kt = bid & 31; nt = bid >> 5;
    } else {
        src = w2; bhi = d_b2hi; blo = d_b2lo; K = DD;
        int r = bid - 128;
        kt = r & 3; nt = r >> 2;
    }
    int tx = threadIdx.x, ty = threadIdx.y;
#pragma unroll
    for (int r = 0; r < 4; r++) {
        int k = kt * 32 + ty + r * 8;
        int n = nt * 32 + tx;
        sm[ty + r * 8][tx] = src[k * 128 + n];
    }
    __syncthreads();
#pragma unroll
    for (int r = 0; r < 4; r++) {
        int n = nt * 32 + ty + r * 8;
        int k = kt * 32 + tx;
        float v = sm[tx][ty + r * 8];
        __nv_bfloat16 h = __float2bfloat16(v);
        bhi[(size_t)n * K + k] = h;
        blo[(size_t)n * K + k] = __float2bfloat16(v - __bfloat162float(h));
    }
}

// ---------------- CSR build -------------------------------------------------
__global__ void k_count(const int* __restrict__ w) {
    int e0 = (blockIdx.x * blockDim.x + threadIdx.x) * 4;
    if (e0 >= EE) return;
    int is64 = d_is64;
#pragma unroll
    for (int j = 0; j < 4; j++) {
        int e = e0 + j;
        if (e < EE) {
            int dd = is64 ? w[2 * (EE + e)] : w[EE + e];
            if ((unsigned)dd < NN) atomicAdd(&d_deg[dd], 1);
        }
    }
}

__global__ void k_scan() {   // 1 block, 1024 threads, shuffle-based
    __shared__ int wsum[32];
    int t = threadIdx.x;
    const int C = 10;
    int base = t * C;
    int v[C];
    int sum = 0;
#pragma unroll
    for (int i = 0; i < C; i++) {
        int idx = base + i;
        v[i] = (idx < NN) ? d_deg[idx] : 0;
        sum += v[i];
    }
    int lane = t & 31, wp = t >> 5;
    int s = sum;
#pragma unroll
    for (int off = 1; off < 32; off <<= 1) {
        int o = __shfl_up_sync(0xFFFFFFFFu, s, off);
        if (lane >= off) s += o;
    }
    if (lane == 31) wsum[wp] = s;
    __syncthreads();
    if (wp == 0) {
        int ws = wsum[lane];
#pragma unroll
        for (int off = 1; off < 32; off <<= 1) {
            int o = __shfl_up_sync(0xFFFFFFFFu, ws, off);
            if (lane >= off) ws += o;
        }
        wsum[lane] = ws;
    }
    __syncthreads();
    int run = s - sum + (wp > 0 ? wsum[wp - 1] : 0);   // exclusive prefix
#pragma unroll
    for (int i = 0; i < C; i++) {
        int idx = base + i;
        if (idx < NN) { d_rowptr[idx] = run; run += v[i]; }
    }
    if (t == 1023) d_rowptr[NN] = wsum[31];
}

// ---------------- fill CSR + per-node scores/dinv (merged) ------------------
__global__ void k_fillnode(const int* __restrict__ w, const float* __restrict__ x) {
    int t = blockIdx.x * blockDim.x + threadIdx.x;
    if (t < NN) {
        float4 xv = ((const float4*)x)[t];
#pragma unroll
        for (int h = 0; h < HH; h++) {
            d_as[t * 8 + h] = xv.x * d_csrc[h * 4 + 0] + xv.y * d_csrc[h * 4 + 1]
                            + xv.z * d_csrc[h * 4 + 2] + xv.w * d_csrc[h * 4 + 3];
            d_ad[t * 8 + h] = xv.x * d_cdst[h * 4 + 0] + xv.y * d_cdst[h * 4 + 1]
                            + xv.z * d_cdst[h * 4 + 2] + xv.w * d_cdst[h * 4 + 3];
        }
        d_dinv[t] = rsqrtf((float)d_deg[t]);
    }
    if (t >= ET) return;
    int is64 = d_is64;
    int s, dd;
    if (t < EE) {
        s  = is64 ? w[2 * t]        : w[t];
        dd = is64 ? w[2 * (EE + t)] : w[EE + t];
    } else {
        s = t - EE; dd = s;           // self loop
    }
    if ((unsigned)dd >= NN || (unsigned)s >= NN) return;
    int pos = atomicAdd(&d_cursor[dd], 1);
    d_colsrc[d_rowptr[dd] + pos] = s;
}

// ---------------- GAT softmax (no max-shift; |e| << 1) + rank-4 agg ---------
// 16 nodes/block (128 threads) -> 625 blocks: raises occupancy ceiling
// (measured occ=21.6% grid-limited at 313 blocks).
__global__ void k_gat(const float* __restrict__ x) {
    int node = blockIdx.x * 16 + (threadIdx.x >> 3);
    int h = threadIdx.x & 7;
    if (node >= NN) return;
    int r0 = d_rowptr[node], r1 = d_rowptr[node + 1];
    float ad = d_ad[node * 8 + h];
    float den = 0.0f;
    float t0 = 0.0f, t1 = 0.0f, t2 = 0.0f, t3 = 0.0f;
    int i = r0;
    for (; i + 2 <= r1; i += 2) {
        int s0 = d_colsrc[i], s1 = d_colsrc[i + 1];
        float e0 = d_as[s0 * 8 + h] + ad;
        float e1 = d_as[s1 * 8 + h] + ad;
        float4 xv0 = ((const float4*)x)[s0];
        float4 xv1 = ((const float4*)x)[s1];
        e0 = e0 > 0.0f ? e0 : 0.2f * e0;
        e1 = e1 > 0.0f ? e1 : 0.2f * e1;
        float ex0 = __expf(e0), ex1 = __expf(e1);
        den += ex0 + ex1;
        t0 += ex0 * xv0.x + ex1 * xv1.x;
        t1 += ex0 * xv0.y + ex1 * xv1.y;
        t2 += ex0 * xv0.z + ex1 * xv1.z;
        t3 += ex0 * xv0.w + ex1 * xv1.w;
    }
    if (i < r1) {
        int s0 = d_colsrc[i];
        float e0 = d_as[s0 * 8 + h] + ad;
        e0 = e0 > 0.0f ? e0 : 0.2f * e0;
        float ex0 = __expf(e0);
        float4 xv0 = ((const float4*)x)[s0];
        den += ex0;
        t0 += ex0 * xv0.x; t1 += ex0 * xv0.y;
        t2 += ex0 * xv0.z; t3 += ex0 * xv0.w;
    }
    float inv = 1.0f / den;
    float* sp = &d_snode[node * 32 + h * 4];
    sp[0] = t0 * inv; sp[1] = t1 * inv; sp[2] = t2 * inv; sp[3] = t3 * inv;
}

// ---------------- split-bf16 mma.sync GEMM (round-12 winner config) ---------
#define OFF_AH 0
#define OFF_AL 2048
#define OFF_BH 4096
#define OFF_BL 10240
#define STAGE_BYTES 16384

__device__ __forceinline__ void gen_a(char* stg, const float* Ssh,
                                      const float* __restrict__ gw,
                                      const float* __restrict__ gb,
                                      int k0, int t) {
    int m = t >> 1, half = t & 1;
    const float* sp = Ssh + m * 36 + ((k0 >> 7) << 2);
    float s0 = sp[0], s1 = sp[1], s2 = sp[2], s3 = sp[3];
    int jb = k0 + half * 8;
    uint32_t hi4[4], lo4[4];
#pragma unroll
    for (int q = 0; q < 4; q++) {
        uint32_t hh = 0, ll = 0;
#pragma unroll
        for (int u = 0; u < 2; u++) {
            int j = jb + q * 2 + u;
            float a = __ldg(gb + j) + s0 * __ldg(gw + j) + s1 * __ldg(gw + HD + j)
                    + s2 * __ldg(gw + 2 * HD + j) + s3 * __ldg(gw + 3 * HD + j);
            float v = gelu_exact(a);
            __nv_bfloat16 h = __float2bfloat16(v);
            __nv_bfloat16 l = __float2bfloat16(v - __bfloat162float(h));
            hh |= (uint32_t)__bfloat16_as_ushort(h) << (u * 16);
            ll |= (uint32_t)__bfloat16_as_ushort(l) << (u * 16);
        }
        hi4[q] = hh; lo4[q] = ll;
    }
    *(uint4*)(stg + OFF_AH + half * 1024 + m * 16) = make_uint4(hi4[0], hi4[1], hi4[2], hi4[3]);
    *(uint4*)(stg + OFF_AL + half * 1024 + m * 16) = make_uint4(lo4[0], lo4[1], lo4[2], lo4[3]);
}

__device__ __forceinline__ void load_b(char* stg, const __nv_bfloat16* gBhi,
                                       const __nv_bfloat16* gBlo, int K, int k0, int t) {
#pragma unroll
    for (int i = 0; i < 4; i++) {
        int idx = t + i * 128;          // 0..511
        int hilo = idx >> 8;
        int r = idx & 255;
        int n = r >> 1, half = r & 1;
        char* dst = stg + (hilo ? OFF_BL : OFF_BH) + n * 48 + half * 16;
        const __nv_bfloat16* src = (hilo ? gBlo : gBhi) + (size_t)n * K + k0 + half * 8;
        cp16(dst, src);
    }
}

__device__ __forceinline__ void load_a(char* stg, int K, int k0, int t, int bm, int M) {
#pragma unroll
    for (int i = 0; i < 2; i++) {
        int idx = t + i * 128;          // 0..255
        int hilo = idx >> 7;
        int r = idx & 127;
        int m = r >> 1, half = r & 1;
        int mg = bm + m; if (mg >= M) mg = M - 1;
        char* dst = stg + (hilo ? OFF_AL : OFF_AH) + half * 1024 + m * 16;
        const __nv_bfloat16* src = (hilo ? d_h1lo : d_h1hi) + (size_t)mg * K + k0 + half * 8;
        cp16(dst, src);
    }
}

__global__ void __launch_bounds__(128) k_mma(int K, int which, int M,
                                             const float* __restrict__ gw,
                                             const float* __restrict__ gb) {
    __shared__ __align__(16) char stage[2 * STAGE_BYTES];
    __shared__ __align__(16) float Ssh[64 * 36];
    int t = threadIdx.x;
    int lane = t & 31, wrp = t >> 5;
    int bm = blockIdx.x * 64;
    const __nv_bfloat16* gBhi = which ? d_b2hi : d_b1hi;
    const __nv_bfloat16* gBlo = which ? d_b2lo : d_b1lo;
    float* C = which ? d_t2 : d_t1;

    if (which == 0) {
        for (int i = t; i < 512; i += 128) {
            int row = i >> 3, q = i & 7;
            int g = bm + row;
            float4 v = (g < M) ? ((const float4*)d_snode)[g * 8 + q]
                               : make_float4(0.f, 0.f, 0.f, 0.f);
            *(float4*)&Ssh[row * 36 + q * 4] = v;
        }
    }
    __syncthreads();

    const int NC = K >> 4;

    // prologue: fill stage 0 (chunk 0)
    load_b(stage, gBhi, gBlo, K, 0, t);
    if (which) load_a(stage, K, 0, t, bm, M);
    asm volatile("cp.async.commit_group;" ::: "memory");
    if (!which) gen_a(stage, Ssh, gw, gb, 0, t);
    asm volatile("cp.async.wait_group 0;" ::: "memory");
    __syncthreads();

    float acc[16][4];
#pragma unroll
    for (int nt = 0; nt < 16; nt++) {
        acc[nt][0] = 0.f; acc[nt][1] = 0.f; acc[nt][2] = 0.f; acc[nt][3] = 0.f;
    }

    uint32_t l15 = lane & 15;
    uint32_t aoff = (wrp * 16 + l15) * 16 + ((uint32_t)(lane >> 4) << 10);
    uint32_t boff = (l15 < 8) ? l15 * 48 : (l15 - 8) * 48 + 16;

    for (int c = 0; c < NC; c++) {
        int cur = c & 1;
        char* stg = stage + cur * STAGE_BYTES;
        if (c + 1 < NC) {
            char* nstg = stage + (cur ^ 1) * STAGE_BYTES;
            int nk0 = (c + 1) << 4;
            load_b(nstg, gBhi, gBlo, K, nk0, t);
            if (which) load_a(nstg, K, nk0, t, bm, M);
            asm volatile("cp.async.commit_group;" ::: "memory");
            if (!which) gen_a(nstg, Ssh, gw, gb, nk0, t);
        }
        uint32_t sb = (uint32_t)__cvta_generic_to_shared(stg);
        uint32_t ah[4], al[4];
        ldsm4(ah, sb + OFF_AH + aoff);
        ldsm4(al, sb + OFF_AL + aoff);
#pragma unroll
        for (int nt = 0; nt < 16; nt++) {
            uint32_t bh[2], bl[2];
            ldsm2(bh, sb + OFF_BH + nt * 384 + boff);
            ldsm2(bl, sb + OFF_BL + nt * 384 + boff);
            mma_bf16(acc[nt], ah, bh);
            mma_bf16(acc[nt], ah, bl);
            mma_bf16(acc[nt], al, bh);
        }
        if (c + 1 < NC)
            asm volatile("cp.async.wait_group 0;" ::: "memory");
        __syncthreads();
    }

    // epilogue: acc -> C (fp32)
    int mrow = bm + wrp * 16 + lane / 4;
    int nbase = (lane % 4) * 2;
#pragma unroll
    for (int nt = 0; nt < 16; nt++) {
        int n0 = nt * 8 + nbase;
        if (mrow < M)
            *(float2*)&C[(size_t)mrow * 128 + n0] = make_float2(acc[nt][0], acc[nt][1]);
        if (mrow + 8 < M)
            *(float2*)&C[(size_t)(mrow + 8) * 128 + n0] = make_float2(acc[nt][2], acc[nt][3]);
    }
}

// ---------------- GCN aggregation (unroll 2 for MLP) -------------------------
template <bool FIRST>
__global__ void k_agg(const float* __restrict__ bias, float* __restrict__ ext_out) {
    const float* tin = FIRST ? d_t1 : d_t2;
    int node = blockIdx.x * 8 + (threadIdx.x >> 5);
    int lane = threadIdx.x & 31;
    if (node >= NN) return;
    int r0 = d_rowptr[node], r1 = d_rowptr[node + 1];
    float4 acc = make_float4(0.f, 0.f, 0.f, 0.f);
    const float4* t4 = (const float4*)tin;
    int i = r0;
    for (; i + 2 <= r1; i += 2) {
        int s0 = d_colsrc[i], s1 = d_colsrc[i + 1];
        float w0 = d_dinv[s0], w1 = d_dinv[s1];
        float4 v0 = t4[s0 * 32 + lane];
        float4 v1 = t4[s1 * 32 + lane];
        acc.x += w0 * v0.x + w1 * v1.x;
        acc.y += w0 * v0.y + w1 * v1.y;
        acc.z += w0 * v0.z + w1 * v1.z;
        acc.w += w0 * v0.w + w1 * v1.w;
    }
    if (i < r1) {
        int s0 = d_colsrc[i];
        float w0 = d_dinv[s0];
        float4 v0 = t4[s0 * 32 + lane];
        acc.x += w0 * v0.x; acc.y += w0 * v0.y;
        acc.z += w0 * v0.z; acc.w += w0 * v0.w;
    }
    float dn = d_dinv[node];
    float4 b = ((const float4*)bias)[lane];
    float4 r;
    r.x = acc.x * dn + b.x;
    r.y = acc.y * dn + b.y;
    r.z = acc.z * dn + b.z;
    r.w = acc.w * dn + b.w;
    if (FIRST) {
        float vv[4];
        vv[0] = gelu_exact(r.x); vv[1] = gelu_exact(r.y);
        vv[2] = gelu_exact(r.z); vv[3] = gelu_exact(r.w);
        int base = node * DD + lane * 4;
#pragma unroll
        for (int c = 0; c < 4; c++) {
            __nv_bfloat16 h = __float2bfloat16(vv[c]);
            d_h1hi[base + c] = h;
            d_h1lo[base + c] = __float2bfloat16(vv[c] - __bfloat162float(h));
        }
    } else {
        ((float4*)ext_out)[node * 32 + lane] = r;
    }
}

// ---------------- launch -----------------------------------------------------
extern "C" void kernel_launch(void* const* d_in, const int* in_sizes, int n_in,
                              void* d_out, int out_size) {
    const float* x       = (const float*)d_in[0];
    const int*   eiw     = (const int*)d_in[1];      // words; dtype detected on device
    const float* gat_w   = (const float*)d_in[2];
    const float* att_src = (const float*)d_in[3];
    const float* att_dst = (const float*)d_in[4];
    const float* gat_b   = (const float*)d_in[5];
    const float* w1      = (const float*)d_in[6];
    const float* b1      = (const float*)d_in[7];
    const float* w2      = (const float*)d_in[8];
    const float* b2      = (const float*)d_in[9];
    float* out = (float*)d_out;

    k_setup<<<(NN + 255) / 256, 256>>>(eiw, gat_w, att_src, att_dst);
    k_prepB<<<144, dim3(32, 8)>>>(w1, w2);
    k_count<<<(EE + 1023) / 1024, 256>>>(eiw);
    k_scan<<<1, 1024>>>();
    k_fillnode<<<(ET + 255) / 256, 256>>>(eiw, x);
    k_gat<<<(NN + 15) / 16, 128>>>(x);
    k_mma<<<(NN + 63) / 64, 128>>>(HD, 0, NN, gat_w, gat_b);
    k_agg<true><<<(NN + 7) / 8, 256>>>(b1, nullptr);
    k_mma<<<(NN + 63) / 64, 128>>>(DD, 1, NN, nullptr, nullptr);
    k_agg<false><<<(NN + 7) / 8, 256>>>(b2, out);
}